// round 15
// baseline (speedup 1.0000x reference)
#include <cuda_runtime.h>
#include <cuda_fp16.h>
#include <cstdint>

#define Bb 4
#define Tt 1024
#define Ss 128
#define Cc 1024
#define NLAYER 8
#define VOC 4096
#define Lseq 2048

#define N_BLC (Bb*Lseq*Cc)
#define N_HF  (Bb*Tt*Cc)

__device__ float g_f32[2*N_BLC + N_HF];       // X, X2, HF
__device__ float g_bqkv[NLAYER*3072];         // fused qkv bias
__device__ __half g_hp[198311936];            // all fp16 planes

#define LWs 8388608u
#define OFF_QKVs 0u
#define OFF_WOs 3145728u
#define OFF_W1s 4194304u
#define OFF_W2s 6291456u

// ---------------- helpers ----------------
__device__ __forceinline__ int gmap(int r) {          // compact idx -> odd row in [B*L)
    return ((r >> 10) << 11) + ((r & 1023) << 1) + 1;
}
__device__ __forceinline__ void ldsm4(uint32_t r[4], const __half* p) {
    uint32_t a = (uint32_t)__cvta_generic_to_shared(p);
    asm volatile("ldmatrix.sync.aligned.m8n8.x4.shared.b16 {%0,%1,%2,%3}, [%4];"
        : "=r"(r[0]), "=r"(r[1]), "=r"(r[2]), "=r"(r[3]) : "r"(a));
}
__device__ __forceinline__ void ldsm4t(uint32_t r[4], const __half* p) {
    uint32_t a = (uint32_t)__cvta_generic_to_shared(p);
    asm volatile("ldmatrix.sync.aligned.m8n8.x4.trans.shared.b16 {%0,%1,%2,%3}, [%4];"
        : "=r"(r[0]), "=r"(r[1]), "=r"(r[2]), "=r"(r[3]) : "r"(a));
}
__device__ __forceinline__ void mma_f16(float c[4], const uint32_t a[4], const uint32_t b[2]) {
    asm volatile("mma.sync.aligned.m16n8k16.row.col.f32.f16.f16.f32 "
        "{%0,%1,%2,%3}, {%4,%5,%6,%7}, {%8,%9}, {%0,%1,%2,%3};"
        : "+f"(c[0]), "+f"(c[1]), "+f"(c[2]), "+f"(c[3])
        : "r"(a[0]), "r"(a[1]), "r"(a[2]), "r"(a[3]), "r"(b[0]), "r"(b[1]));
}
__device__ __forceinline__ void cpa16(__half* dst, const __half* src) {
    uint32_t d = (uint32_t)__cvta_generic_to_shared(dst);
    asm volatile("cp.async.cg.shared.global [%0], [%1], 16;" :: "r"(d), "l"(src));
}
__device__ __forceinline__ float fast_exp(float x) {
    x = fmaxf(x, -80.f);
    float y = x * 1.44269504088896f;
    float t = y + 12582912.f;
    int ni = __float_as_int(t) - 0x4B400000;
    float f = y - (t - 12582912.f);
    float p = 1.33335581e-3f;
    p = fmaf(p, f, 9.61812910e-3f);
    p = fmaf(p, f, 5.55041087e-2f);
    p = fmaf(p, f, 2.40226507e-1f);
    p = fmaf(p, f, 6.93147180e-1f);
    p = fmaf(p, f, 1.0f);
    return p * __int_as_float((ni + 127) << 23);
}

// ---------------- GEMM: out = act((A)@W16^T + bias)(+res) ----------------
// CTA 128x128, BK=32, 8 warps of 32x64, 3-stage cp.async.
// GATH: A-rows and res-rows read through odd-row map (out rows stay compact).
template<int ACT, bool HASBIAS, bool HASRES, int PL, bool GATH>
__global__ __launch_bounds__(256, 2) void gemm_hk(
    const __half* __restrict__ Ah, const __half* __restrict__ Wh,
    const float* __restrict__ bias, const float* __restrict__ res,
    float* __restrict__ out, __half* __restrict__ outH,
    int M, int N, int K)
{
    extern __shared__ __half sm[];
    const int TILE = 128*40;
    const int STH = 2 * TILE;
    int tid = threadIdx.x, lane = tid & 31, warp = tid >> 5;
    int bm = blockIdx.y * 128, bn = blockIdx.x * 128;
    int wm = (warp >> 1) * 32, wn = (warp & 1) * 64;

    float acc[2][8][4];
    #pragma unroll
    for (int i = 0; i < 2; i++)
        #pragma unroll
        for (int j = 0; j < 8; j++)
            #pragma unroll
            for (int q = 0; q < 4; q++) acc[i][j][q] = 0.f;

    int niter = K >> 5;

    #define ISSUE(ST, K0) do {                                                  \
        int _k0 = (K0);                                                         \
        _Pragma("unroll")                                                       \
        for (int _i = 0; _i < 4; _i++) {                                        \
            int _id = tid + (_i << 8);                                          \
            int _tile = _id >> 9;                                               \
            int _r = (_id >> 2) & 127;                                          \
            int _c = (_id & 3) << 3;                                            \
            const __half* _src;                                                 \
            if (_tile == 0) {                                                   \
                int _row = GATH ? gmap(bm + _r) : (bm + _r);                    \
                _src = Ah + (size_t)_row * K + _k0 + _c;                        \
            } else {                                                            \
                _src = Wh + (size_t)(bn + _r) * K + _k0 + _c;                   \
            }                                                                   \
            cpa16(sm + (ST)*STH + _tile*TILE + _r*40 + _c, _src);               \
        }                                                                       \
        asm volatile("cp.async.commit_group;" ::: "memory");                    \
    } while (0)

    ISSUE(0, 0);
    if (niter > 1) ISSUE(1, 32);
    for (int it = 0; it < niter; ++it) {
        if (it + 1 < niter) {
            asm volatile("cp.async.wait_group 1;" ::: "memory");
        } else {
            asm volatile("cp.async.wait_group 0;" ::: "memory");
        }
        __syncthreads();
        if (it + 2 < niter) ISSUE((it + 2) % 3, (it + 2) << 5);

        int st = it % 3;
        const __half* AshH = sm + st*STH;
        const __half* BshW = AshH + TILE;

        #pragma unroll
        for (int ks = 0; ks < 2; ks++) {
            uint32_t aH[2][4];
            #pragma unroll
            for (int mi = 0; mi < 2; mi++) {
                int row = wm + mi*16 + (lane & 15);
                int col = ks*16 + ((lane >> 4) << 3);
                ldsm4(aH[mi], &AshH[row*40 + col]);
            }
            uint32_t bW[8][2];
            #pragma unroll
            for (int pi = 0; pi < 4; pi++) {
                int nr = wn + pi*16 + ((lane >> 4) << 3) + (lane & 7);
                int kc = ks*16 + (((lane >> 3) & 1) << 3);
                uint32_t t[4];
                ldsm4(t, &BshW[nr*40 + kc]);
                bW[2*pi][0] = t[0]; bW[2*pi][1] = t[1];
                bW[2*pi+1][0] = t[2]; bW[2*pi+1][1] = t[3];
            }
            #pragma unroll
            for (int mi = 0; mi < 2; mi++)
                #pragma unroll
                for (int nj = 0; nj < 8; nj++)
                    mma_f16(acc[mi][nj], aH[mi], bW[nj]);
        }
    }
    #undef ISSUE

    int g = lane >> 2, tg = lane & 3;
    #pragma unroll
    for (int mi = 0; mi < 2; mi++)
        #pragma unroll
        for (int nj = 0; nj < 8; nj++) {
            int r0 = bm + wm + mi*16 + g;
            int c0 = bn + wn + nj*8 + tg*2;
            float v[4];
            #pragma unroll
            for (int q = 0; q < 4; q++) {
                float x = acc[mi][nj][q];
                if (HASBIAS) x += bias[c0 + (q & 1)];
                if (ACT == 1) x = tanhf(x);
                else if (ACT == 2) x = 0.5f * x * (1.0f + erff(x * 0.70710678f));
                v[q] = x;
            }
            if (PL == 1) {
                #pragma unroll
                for (int h2 = 0; h2 < 2; h2++) {
                    int r = r0 + h2*8;
                    __half2 hh;
                    hh.x = __float2half_rn(v[2*h2]);
                    hh.y = __float2half_rn(v[2*h2+1]);
                    *(__half2*)&outH[(size_t)r*N + c0] = hh;
                }
            } else {
                #pragma unroll
                for (int q = 0; q < 4; q++) {
                    int r = r0 + (q >> 1) * 8, c = c0 + (q & 1);
                    float x = v[q];
                    if (HASRES) {
                        int rr = GATH ? gmap(r) : r;
                        x += res[(size_t)rr * N + c];
                    }
                    out[(size_t)r * N + c] = x;
                }
            }
        }
}

// ---------------- standalone LayerNorm -> fp16 hi plane ----------------
__global__ __launch_bounds__(256) void ln_kernel(
    const float* __restrict__ x, const float* __restrict__ g,
    const float* __restrict__ b, __half* __restrict__ oh, int gather)
{
    int row = blockIdx.x;
    int src = gather ? ((row / Tt) * Lseq + 2 * (row % Tt) + 1) : row;
    float4 v = ((const float4*)(x + (size_t)src * Cc))[threadIdx.x];
    float s = v.x + v.y + v.z + v.w;
    float q = v.x*v.x + v.y*v.y + v.z*v.z + v.w*v.w;
    #pragma unroll
    for (int o = 16; o; o >>= 1) {
        s += __shfl_xor_sync(0xffffffffu, s, o);
        q += __shfl_xor_sync(0xffffffffu, q, o);
    }
    __shared__ float ss[8], sq[8];
    int w = threadIdx.x >> 5;
    if ((threadIdx.x & 31) == 0) { ss[w] = s; sq[w] = q; }
    __syncthreads();
    s = 0.f; q = 0.f;
    #pragma unroll
    for (int i = 0; i < 8; i++) { s += ss[i]; q += sq[i]; }
    float mean = s * (1.0f / Cc);
    float rstd = rsqrtf(q * (1.0f / Cc) - mean * mean + 1e-5f);
    float4 gv = ((const float4*)g)[threadIdx.x];
    float4 bv = ((const float4*)b)[threadIdx.x];
    size_t base = (size_t)row * Cc + threadIdx.x * 4;
    __half2 p;
    p.x = __float2half_rn((v.x - mean) * rstd * gv.x + bv.x);
    p.y = __float2half_rn((v.y - mean) * rstd * gv.y + bv.y);
    *(__half2*)&oh[base] = p;
    p.x = __float2half_rn((v.z - mean) * rstd * gv.z + bv.z);
    p.y = __float2half_rn((v.w - mean) * rstd * gv.w + bv.w);
    *(__half2*)&oh[base+2] = p;
}

// ---------------- token assembly ----------------
__global__ __launch_bounds__(256) void assemble_kernel(
    const float* __restrict__ SE, const int* __restrict__ actions,
    const int* __restrict__ tsteps, const float* __restrict__ act_table,
    const float* __restrict__ pos_emb, const float* __restrict__ gpe_table,
    float* __restrict__ x)
{
    int bt = blockIdx.x;
    int b = bt / Tt, t = bt % Tt;
    int a = actions[bt];
    int ts = tsteps[bt];
    size_t row0 = (size_t)(b * Lseq + 2*t) * Cc;
    for (int c = threadIdx.x; c < Cc; c += 256) {
        float gp = gpe_table[(size_t)ts * Cc + c];
        x[row0 + c]      = SE[(size_t)bt * Cc + c] + gp + pos_emb[(size_t)(2*t) * Cc + c];
        x[row0 + Cc + c] = tanhf(act_table[(size_t)a * Cc + c]) + gp + pos_emb[(size_t)(2*t+1) * Cc + c];
    }
}

// ---------------- MMA flash attention: 128-row Q tiles, 2-stage KV pipeline ----------------
// grid(L/128, B*H), 256 thr (8 warps x 16 q-rows).
__global__ __launch_bounds__(256) void attn_kernel(
    const __half* __restrict__ QKVH, __half* __restrict__ OutH)
{
    extern __shared__ __half smb[];
    __half* sQ  = smb;                 // 128*72
    __half* sK0 = smb + 9216;
    __half* sK1 = smb + 9216 + 4608;
    __half* sV0 = smb + 9216 + 2*4608;
    __half* sV1 = smb + 9216 + 3*4608;

    int tid = threadIdx.x, lane = tid & 31, wid = tid >> 5;
    int b = blockIdx.y >> 4, h = blockIdx.y & 15;
    int q0 = blockIdx.x * 128;
    size_t gbase = (size_t)b * Lseq * 3072 + h * 64;

    #pragma unroll
    for (int i = 0; i < 4; i++) {
        int id = tid + i*256;
        int r = id >> 3;               // 0..127
        int c = (id & 7) << 3;
        cpa16(sQ + r*72 + c, QKVH + gbase + (size_t)(q0 + r)*3072 + c);
    }
    asm volatile("cp.async.commit_group;" ::: "memory");

    #define ISSUE_KV(J0, BK, BV) do {                                           \
        _Pragma("unroll")                                                       \
        for (int _i = 0; _i < 4; _i++) {                                        \
            int _id = tid + _i*256;                                             \
            int _pl = _id >> 9;                                                 \
            int _r = (_id >> 3) & 63;                                           \
            int _c = (_id & 7) << 3;                                            \
            cpa16((_pl ? (BV) : (BK)) + _r*72 + _c,                             \
                  QKVH + gbase + (size_t)((J0) + _r)*3072 + (_pl ? 2048 : 1024) + _c); \
        }                                                                       \
        asm volatile("cp.async.commit_group;" ::: "memory");                    \
    } while (0)

    ISSUE_KV(0, sK0, sV0);

    float m0 = -1e30f, m1 = -1e30f, lsum0 = 0.f, lsum1 = 0.f;
    float O[8][4];
    #pragma unroll
    for (int f = 0; f < 8; f++)
        #pragma unroll
        for (int q = 0; q < 4; q++) O[f][q] = 0.f;

    int g = lane >> 2, tg = lane & 3;
    int wq = wid * 16;
    int row0 = q0 + wq + g, row1 = row0 + 8;
    int ntiles = 2 * blockIdx.x + 2;

    for (int kt = 0; kt < ntiles; kt++) {
        if (kt + 1 < ntiles) {
            if ((kt + 1) & 1) ISSUE_KV((kt+1)*64, sK1, sV1);
            else              ISSUE_KV((kt+1)*64, sK0, sV0);
            asm volatile("cp.async.wait_group 1;" ::: "memory");
        } else {
            asm volatile("cp.async.wait_group 0;" ::: "memory");
        }
        __syncthreads();
        const __half* sKH = (kt & 1) ? sK1 : sK0;
        const __half* sVH = (kt & 1) ? sV1 : sV0;
        int j0 = kt * 64;

        float S[8][4];
        #pragma unroll
        for (int f = 0; f < 8; f++)
            #pragma unroll
            for (int q = 0; q < 4; q++) S[f][q] = 0.f;

        #pragma unroll
        for (int ks = 0; ks < 4; ks++) {
            int arow = wq + (lane & 15);
            int acol = ks*16 + ((lane >> 4) << 3);
            uint32_t aH[4];
            ldsm4(aH, sQ + arow*72 + acol);
            #pragma unroll
            for (int nb = 0; nb < 4; nb++) {
                int nr = nb*16 + ((lane >> 4) << 3) + (lane & 7);
                int kc = ks*16 + (((lane >> 3) & 1) << 3);
                uint32_t tK[4];
                ldsm4(tK, sKH + nr*72 + kc);
                uint32_t b0[2] = {tK[0], tK[1]}, b1[2] = {tK[2], tK[3]};
                mma_f16(S[2*nb],   aH, b0);
                mma_f16(S[2*nb+1], aH, b1);
            }
        }

        #pragma unroll
        for (int f = 0; f < 8; f++) {
            int kcol = j0 + f*8 + tg*2;
            float v0 = S[f][0]*0.125f; if (kcol   > row0) v0 = -1e30f;
            float v1 = S[f][1]*0.125f; if (kcol+1 > row0) v1 = -1e30f;
            float v2 = S[f][2]*0.125f; if (kcol   > row1) v2 = -1e30f;
            float v3 = S[f][3]*0.125f; if (kcol+1 > row1) v3 = -1e30f;
            S[f][0] = v0; S[f][1] = v1; S[f][2] = v2; S[f][3] = v3;
        }
        float r0m = -1e30f, r1m = -1e30f;
        #pragma unroll
        for (int f = 0; f < 8; f++) {
            r0m = fmaxf(r0m, fmaxf(S[f][0], S[f][1]));
            r1m = fmaxf(r1m, fmaxf(S[f][2], S[f][3]));
        }
        r0m = fmaxf(r0m, __shfl_xor_sync(0xffffffffu, r0m, 1));
        r0m = fmaxf(r0m, __shfl_xor_sync(0xffffffffu, r0m, 2));
        r1m = fmaxf(r1m, __shfl_xor_sync(0xffffffffu, r1m, 1));
        r1m = fmaxf(r1m, __shfl_xor_sync(0xffffffffu, r1m, 2));
        float mn0 = fmaxf(m0, r0m), mn1 = fmaxf(m1, r1m);
        float a0 = fast_exp(m0 - mn0), a1 = fast_exp(m1 - mn1);
        m0 = mn0; m1 = mn1;

        float s0 = 0.f, s1 = 0.f;
        #pragma unroll
        for (int f = 0; f < 8; f++) {
            float p0 = fast_exp(S[f][0] - mn0);
            float p1 = fast_exp(S[f][1] - mn0);
            float p2 = fast_exp(S[f][2] - mn1);
            float p3 = fast_exp(S[f][3] - mn1);
            S[f][0] = p0; S[f][1] = p1; S[f][2] = p2; S[f][3] = p3;
            s0 += p0 + p1; s1 += p2 + p3;
        }
        s0 += __shfl_xor_sync(0xffffffffu, s0, 1);
        s0 += __shfl_xor_sync(0xffffffffu, s0, 2);
        s1 += __shfl_xor_sync(0xffffffffu, s1, 1);
        s1 += __shfl_xor_sync(0xffffffffu, s1, 2);
        lsum0 = lsum0 * a0 + s0;
        lsum1 = lsum1 * a1 + s1;
        #pragma unroll
        for (int f = 0; f < 8; f++) {
            O[f][0] *= a0; O[f][1] *= a0;
            O[f][2] *= a1; O[f][3] *= a1;
        }

        #pragma unroll
        for (int ks2 = 0; ks2 < 4; ks2++) {
            uint32_t pH[4];
            #pragma unroll
            for (int hf = 0; hf < 2; hf++) {
                int f = 2*ks2 + hf;
                __half2 t;
                t.x = __float2half_rn(S[f][0]);
                t.y = __float2half_rn(S[f][1]);
                pH[hf*2+0] = *(uint32_t*)&t;
                t.x = __float2half_rn(S[f][2]);
                t.y = __float2half_rn(S[f][3]);
                pH[hf*2+1] = *(uint32_t*)&t;
            }
            int vrow = ks2*16 + (lane & 15);
            #pragma unroll
            for (int nb = 0; nb < 4; nb++) {
                int vcol = nb*16 + ((lane >> 4) << 3);
                uint32_t tV[4];
                ldsm4t(tV, sVH + vrow*72 + vcol);
                uint32_t b0[2] = {tV[0], tV[1]}, b1[2] = {tV[2], tV[3]};
                mma_f16(O[2*nb],   pH, b0);
                mma_f16(O[2*nb+1], pH, b1);
            }
        }
        __syncthreads();
    }
    #undef ISSUE_KV

    float rl0 = 1.f / lsum0, rl1 = 1.f / lsum1;
    size_t t0 = (size_t)(b*Lseq + row0), t1 = (size_t)(b*Lseq + row1);
    #pragma unroll
    for (int f = 0; f < 8; f++) {
        int gcol = h*64 + f*8 + tg*2;
        __half2 ph;
        ph.x = __float2half_rn(O[f][0]*rl0);
        ph.y = __float2half_rn(O[f][1]*rl0);
        *(__half2*)&OutH[t0*Cc + gcol] = ph;
        ph.x = __float2half_rn(O[f][2]*rl1);
        ph.y = __float2half_rn(O[f][3]*rl1);
        *(__half2*)&OutH[t1*Cc + gcol] = ph;
    }
}

// ---------------- weight transpose + fp16 (generic) ----------------
__global__ __launch_bounds__(256) void wsplit_kernel(
    const float* __restrict__ W, __half* __restrict__ Wh, int K, int N,
    size_t inStride, size_t outStride)
{
    const float* Wz = W + (size_t)blockIdx.z * inStride;
    __half* Whz = Wh + (size_t)blockIdx.z * outStride;
    __shared__ float tile[32][33];
    int k0 = blockIdx.y * 32, n0 = blockIdx.x * 32;
    int tx = threadIdx.x & 31, ty = threadIdx.x >> 5;
    #pragma unroll
    for (int r = ty; r < 32; r += 8)
        tile[r][tx] = Wz[(size_t)(k0 + r) * N + n0 + tx];
    __syncthreads();
    #pragma unroll
    for (int r = ty; r < 32; r += 8)
        Whz[(size_t)(n0 + r) * K + k0 + tx] = __float2half_rn(tile[tx][r]);
}

// ---------------- merged wsplit: Wq/Wk/Wv/Wo ----------------
__global__ __launch_bounds__(256) void wsplit4_kernel(
    const float* __restrict__ Wq, const float* __restrict__ Wk,
    const float* __restrict__ Wv, const float* __restrict__ Wo,
    __half* __restrict__ wAll)
{
    int z = blockIdx.z;
    int m = z >> 3, lyr = z & 7;
    const float* W = (m == 0 ? Wq : m == 1 ? Wk : m == 2 ? Wv : Wo)
                   + (size_t)lyr * Cc * Cc;
    uint32_t doff = (m == 0) ? OFF_QKVs
                  : (m == 1) ? OFF_QKVs + 1024u*Cc
                  : (m == 2) ? OFF_QKVs + 2048u*Cc : OFF_WOs;
    __half* out = wAll + (size_t)lyr * LWs + doff;

    __shared__ float tile[32][33];
    int k0 = blockIdx.y * 32, n0 = blockIdx.x * 32;
    int tx = threadIdx.x & 31, ty = threadIdx.x >> 5;
    #pragma unroll
    for (int r = ty; r < 32; r += 8)
        tile[r][tx] = W[(size_t)(k0 + r) * Cc + n0 + tx];
    __syncthreads();
    #pragma unroll
    for (int r = ty; r < 32; r += 8)
        out[(size_t)(n0 + r) * Cc + k0 + tx] = __float2half_rn(tile[tx][r]);
}

// ---------------- merged wsplit: W1 + W2 ----------------
__global__ __launch_bounds__(256) void wsplit12_kernel(
    const float* __restrict__ W1, const float* __restrict__ W2,
    __half* __restrict__ wAll)
{
    int z = blockIdx.z;
    int m = z >> 3, lyr = z & 7;
    int K = m ? 2048 : 1024;
    int N = m ? 1024 : 2048;
    int k0 = blockIdx.y * 32, n0 = blockIdx.x * 32;
    if (k0 >= K || n0 >= N) return;
    const float* W = (m ? W2 : W1) + (size_t)lyr * 2097152;
    __half* out = wAll + (size_t)lyr * LWs + (m ? OFF_W2s : OFF_W1s);

    __shared__ float tile[32][33];
    int tx = threadIdx.x & 31, ty = threadIdx.x >> 5;
    #pragma unroll
    for (int r = ty; r < 32; r += 8)
        tile[r][tx] = W[(size_t)(k0 + r) * N + n0 + tx];
    __syncthreads();
    #pragma unroll
    for (int r = ty; r < 32; r += 8)
        out[(size_t)(n0 + r) * K + k0 + tx] = __float2half_rn(tile[tx][r]);
}

// ---------------- fused QKV bias concat ----------------
__global__ __launch_bounds__(256) void bcat_kernel(
    const float* __restrict__ bq, const float* __restrict__ bk,
    const float* __restrict__ bv, float* __restrict__ outb)
{
    int i = blockIdx.x * 256 + threadIdx.x;
    if (i < NLAYER * 3072) {
        int lyr = i / 3072, c = i % 3072;
        float v = (c < 1024) ? bq[lyr*1024 + c]
                : (c < 2048) ? bk[lyr*1024 + c - 1024]
                             : bv[lyr*1024 + c - 2048];
        outb[i] = v;
    }
}

// ---------------- elementwise fp16 round (states) ----------------
__global__ __launch_bounds__(256) void esplit1_kernel(
    const float* __restrict__ x, __half* __restrict__ h, int n)
{
    int i = (blockIdx.x * 256 + threadIdx.x) * 4;
    if (i < n) {
        float4 v = *(const float4*)&x[i];
        __half2 p;
        p.x = __float2half_rn(v.x); p.y = __float2half_rn(v.y);
        *(__half2*)&h[i] = p;
        p.x = __float2half_rn(v.z); p.y = __float2half_rn(v.w);
        *(__half2*)&h[i+2] = p;
    }
}

// ---------------- launcher ----------------
extern "C" void kernel_launch(void* const* d_in, const int* in_sizes, int n_in,
                              void* d_out, int out_size) {
    const float* states   = (const float*)d_in[0];
    const int*   actions  = (const int*)d_in[1];
    const int*   tsteps   = (const int*)d_in[2];
    const float* W_se     = (const float*)d_in[3];
    const float* b_se     = (const float*)d_in[4];
    const float* act_tab  = (const float*)d_in[5];
    const float* pos_emb  = (const float*)d_in[6];
    const float* gpe      = (const float*)d_in[7];
    const float* ln1_g    = (const float*)d_in[8];
    const float* ln1_b    = (const float*)d_in[9];
    const float* Wq       = (const float*)d_in[10];
    const float* bq       = (const float*)d_in[11];
    const float* Wk       = (const float*)d_in[12];
    const float* bk       = (const float*)d_in[13];
    const float* Wv       = (const float*)d_in[14];
    const float* bv       = (const float*)d_in[15];
    const float* Wo       = (const float*)d_in[16];
    const float* bo       = (const float*)d_in[17];
    const float* ln2_g    = (const float*)d_in[18];
    const float* ln2_b    = (const float*)d_in[19];
    const float* W1       = (const float*)d_in[20];
    const float* b1       = (const float*)d_in[21];
    const float* W2       = (const float*)d_in[22];
    const float* b2       = (const float*)d_in[23];
    const float* lnf_g    = (const float*)d_in[24];
    const float* lnf_b    = (const float*)d_in[25];
    const float* W_head   = (const float*)d_in[26];
    float* out = (float*)d_out;

    float* F = nullptr;
    cudaGetSymbolAddress((void**)&F, g_f32);
    float* BQKV = nullptr;
    cudaGetSymbolAddress((void**)&BQKV, g_bqkv);
    __half* HP = nullptr;
    cudaGetSymbolAddress((void**)&HP, g_hp);

    float* X  = F;
    float* X2 = X  + N_BLC;
    float* HF = X2 + N_BLC;

    size_t off = 0;
    auto take = [&](size_t n) { __half* p = HP + off; off += n; return p; };
    __half *stH = take(524288);
    __half *wseH = take(131072);
    __half *wAll = take(67108864);
    __half *hdH = take(4194304);
    __half *HbH = take(N_BLC);
    __half *AOH = take(N_BLC);
    __half *MIDH = take(2*N_BLC);
    __half *HFH = take(N_HF);
    __half *QKVH = take(3*N_BLC);

    const int GSM1 = 3*2*5120*2;        // 61440 B
    const int ATSM = (9216 + 4*4608)*2; // 55296 B
    cudaFuncSetAttribute(gemm_hk<1,true,false,0,false>, cudaFuncAttributeMaxDynamicSharedMemorySize, GSM1);
    cudaFuncSetAttribute(gemm_hk<0,true,false,1,false>, cudaFuncAttributeMaxDynamicSharedMemorySize, GSM1);
    cudaFuncSetAttribute(gemm_hk<0,true,true,0,false>,  cudaFuncAttributeMaxDynamicSharedMemorySize, GSM1);
    cudaFuncSetAttribute(gemm_hk<0,true,true,0,true>,   cudaFuncAttributeMaxDynamicSharedMemorySize, GSM1);
    cudaFuncSetAttribute(gemm_hk<2,true,false,1,false>, cudaFuncAttributeMaxDynamicSharedMemorySize, GSM1);
    cudaFuncSetAttribute(gemm_hk<0,false,false,0,false>,cudaFuncAttributeMaxDynamicSharedMemorySize, GSM1);
    cudaFuncSetAttribute(attn_kernel, cudaFuncAttributeMaxDynamicSharedMemorySize, ATSM);

    const int Mx = Bb * Lseq;   // 8192
    const int Mh = Bb * Tt;     // 4096
    dim3 thr(256);

    // ---- prep ----
    bcat_kernel<<<96, thr>>>(bq, bk, bv, BQKV);
    esplit1_kernel<<<512, thr>>>(states, stH, Mh * Ss);
    wsplit_kernel<<<dim3(Cc/32, Ss/32, 1), thr>>>(W_se, wseH, Ss, Cc, 0, 0);
    wsplit4_kernel<<<dim3(32, 32, 32), thr>>>(Wq, Wk, Wv, Wo, wAll);
    wsplit12_kernel<<<dim3(64, 64, 16), thr>>>(W1, W2, wAll);

    // ---- state encoder + token assembly ----
    gemm_hk<1,true,false,0,false><<<dim3(Cc/128, Mh/128), thr, GSM1>>>(
        stH, wseH, b_se, nullptr, HF, nullptr, Mh, Cc, Ss);
    assemble_kernel<<<Mh, thr>>>(HF, actions, tsteps, act_tab, pos_emb, gpe, X);

    for (int lyr = 0; lyr < NLAYER; lyr++) {
        __half* wqkv = wAll + lyr*LWs + OFF_QKVs;
        __half* wo   = wAll + lyr*LWs + OFF_WOs;
        __half* w1   = wAll + lyr*LWs + OFF_W1s;
        __half* w2   = wAll + lyr*LWs + OFF_W2s;
        bool last = (lyr == NLAYER - 1);

        ln_kernel<<<Mx, thr>>>(X, ln1_g + lyr*Cc, ln1_b + lyr*Cc, HbH, 0);
        gemm_hk<0,true,false,1,false><<<dim3(3072/128, Mx/128), thr, GSM1>>>(
            HbH, wqkv, BQKV + lyr*3072, nullptr, nullptr, QKVH, Mx, 3072, Cc);
        attn_kernel<<<dim3(Lseq/128, Bb*16), thr, ATSM>>>(QKVH, AOH);
        if (!last) {
            gemm_hk<0,true,true,0,false><<<dim3(Cc/128, Mx/128), thr, GSM1>>>(
                AOH, wo, bo + lyr*Cc, X, X2, nullptr, Mx, Cc, Cc);
            ln_kernel<<<Mx, thr>>>(X2, ln2_g + lyr*Cc, ln2_b + lyr*Cc, HbH, 0);
            gemm_hk<2,true,false,1,false><<<dim3(2*Cc/128, Mx/128), thr, GSM1>>>(
                HbH, w1, b1 + lyr*2*Cc, nullptr, nullptr, MIDH, Mx, 2*Cc, Cc);
            gemm_hk<0,true,true,0,false><<<dim3(Cc/128, Mx/128), thr, GSM1>>>(
                MIDH, w2, b2 + lyr*Cc, X2, X, nullptr, Mx, Cc, 2*Cc);
        } else {
            // last layer: only odd rows survive -> compact M=4096 path
            gemm_hk<0,true,true,0,true><<<dim3(Cc/128, Mh/128), thr, GSM1>>>(
                AOH, wo, bo + lyr*Cc, X, X2, nullptr, Mh, Cc, Cc);
            ln_kernel<<<Mh, thr>>>(X2, ln2_g + lyr*Cc, ln2_b + lyr*Cc, HbH, 0);
            gemm_hk<2,true,false,1,false><<<dim3(2*Cc/128, Mh/128), thr, GSM1>>>(
                HbH, w1, b1 + lyr*2*Cc, nullptr, nullptr, MIDH, Mh, 2*Cc, Cc);
            gemm_hk<0,true,true,0,false><<<dim3(Cc/128, Mh/128), thr, GSM1>>>(
                MIDH, w2, b2 + lyr*Cc, X2, HF, nullptr, Mh, Cc, 2*Cc);
        }
    }

    wsplit_kernel<<<dim3(VOC/32, Cc/32, 1), thr>>>(W_head, hdH, Cc, VOC, 0, 0);
    ln_kernel<<<Mh, thr>>>(HF, lnf_g, lnf_b, HFH, 0);
    gemm_hk<0,false,false,0,false><<<dim3(VOC/128, Mh/128), thr, GSM1>>>(
        HFH, hdH, nullptr, nullptr, out, nullptr, Mh, VOC, Cc);
}

// round 16
// speedup vs baseline: 1.0475x; 1.0475x over previous
#include <cuda_runtime.h>
#include <cuda_fp16.h>
#include <cstdint>

#define Bb 4
#define Tt 1024
#define Ss 128
#define Cc 1024
#define NLAYER 8
#define VOC 4096
#define Lseq 2048

#define N_BLC (Bb*Lseq*Cc)
#define N_HF  (Bb*Tt*Cc)

__device__ float g_f32[2*N_BLC + N_HF];       // X, X2, HF
__device__ float g_bqkv[NLAYER*3072];         // fused qkv bias
__device__ __half g_hp[198311936];            // all fp16 planes

#define LWs 8388608u
#define OFF_QKVs 0u
#define OFF_WOs 3145728u
#define OFF_W1s 4194304u
#define OFF_W2s 6291456u

// ---------------- helpers ----------------
__device__ __forceinline__ int gmap(int r) {          // compact idx -> odd row in [B*L)
    return ((r >> 10) << 11) + ((r & 1023) << 1) + 1;
}
__device__ __forceinline__ void ldsm4(uint32_t r[4], const __half* p) {
    uint32_t a = (uint32_t)__cvta_generic_to_shared(p);
    asm volatile("ldmatrix.sync.aligned.m8n8.x4.shared.b16 {%0,%1,%2,%3}, [%4];"
        : "=r"(r[0]), "=r"(r[1]), "=r"(r[2]), "=r"(r[3]) : "r"(a));
}
__device__ __forceinline__ void ldsm4t(uint32_t r[4], const __half* p) {
    uint32_t a = (uint32_t)__cvta_generic_to_shared(p);
    asm volatile("ldmatrix.sync.aligned.m8n8.x4.trans.shared.b16 {%0,%1,%2,%3}, [%4];"
        : "=r"(r[0]), "=r"(r[1]), "=r"(r[2]), "=r"(r[3]) : "r"(a));
}
__device__ __forceinline__ void mma_f16(float c[4], const uint32_t a[4], const uint32_t b[2]) {
    asm volatile("mma.sync.aligned.m16n8k16.row.col.f32.f16.f16.f32 "
        "{%0,%1,%2,%3}, {%4,%5,%6,%7}, {%8,%9}, {%0,%1,%2,%3};"
        : "+f"(c[0]), "+f"(c[1]), "+f"(c[2]), "+f"(c[3])
        : "r"(a[0]), "r"(a[1]), "r"(a[2]), "r"(a[3]), "r"(b[0]), "r"(b[1]));
}
__device__ __forceinline__ void cpa16(__half* dst, const __half* src) {
    uint32_t d = (uint32_t)__cvta_generic_to_shared(dst);
    asm volatile("cp.async.cg.shared.global [%0], [%1], 16;" :: "r"(d), "l"(src));
}
__device__ __forceinline__ float fast_exp(float x) {
    x = fmaxf(x, -80.f);
    float y = x * 1.44269504088896f;
    float t = y + 12582912.f;
    int ni = __float_as_int(t) - 0x4B400000;
    float f = y - (t - 12582912.f);
    float p = 1.33335581e-3f;
    p = fmaf(p, f, 9.61812910e-3f);
    p = fmaf(p, f, 5.55041087e-2f);
    p = fmaf(p, f, 2.40226507e-1f);
    p = fmaf(p, f, 6.93147180e-1f);
    p = fmaf(p, f, 1.0f);
    return p * __int_as_float((ni + 127) << 23);
}

// ---------------- GEMM: out = act((A)@W16^T + bias)(+res) ----------------
// CTA 128x128, BK=32, 8 warps of 32x64, 3-stage cp.async.
// GATH: A-rows and res-rows read through odd-row map (out rows stay compact).
template<int ACT, bool HASBIAS, bool HASRES, int PL, bool GATH>
__global__ __launch_bounds__(256, 2) void gemm_hk(
    const __half* __restrict__ Ah, const __half* __restrict__ Wh,
    const float* __restrict__ bias, const float* __restrict__ res,
    float* __restrict__ out, __half* __restrict__ outH,
    int M, int N, int K)
{
    extern __shared__ __half sm[];
    const int TILE = 128*40;
    const int STH = 2 * TILE;
    int tid = threadIdx.x, lane = tid & 31, warp = tid >> 5;
    int bm = blockIdx.y * 128, bn = blockIdx.x * 128;
    int wm = (warp >> 1) * 32, wn = (warp & 1) * 64;

    float acc[2][8][4];
    #pragma unroll
    for (int i = 0; i < 2; i++)
        #pragma unroll
        for (int j = 0; j < 8; j++)
            #pragma unroll
            for (int q = 0; q < 4; q++) acc[i][j][q] = 0.f;

    int niter = K >> 5;

    #define ISSUE(ST, K0) do {                                                  \
        int _k0 = (K0);                                                         \
        _Pragma("unroll")                                                       \
        for (int _i = 0; _i < 4; _i++) {                                        \
            int _id = tid + (_i << 8);                                          \
            int _tile = _id >> 9;                                               \
            int _r = (_id >> 2) & 127;                                          \
            int _c = (_id & 3) << 3;                                            \
            const __half* _src;                                                 \
            if (_tile == 0) {                                                   \
                int _row = GATH ? gmap(bm + _r) : (bm + _r);                    \
                _src = Ah + (size_t)_row * K + _k0 + _c;                        \
            } else {                                                            \
                _src = Wh + (size_t)(bn + _r) * K + _k0 + _c;                   \
            }                                                                   \
            cpa16(sm + (ST)*STH + _tile*TILE + _r*40 + _c, _src);               \
        }                                                                       \
        asm volatile("cp.async.commit_group;" ::: "memory");                    \
    } while (0)

    ISSUE(0, 0);
    if (niter > 1) ISSUE(1, 32);
    for (int it = 0; it < niter; ++it) {
        if (it + 1 < niter) {
            asm volatile("cp.async.wait_group 1;" ::: "memory");
        } else {
            asm volatile("cp.async.wait_group 0;" ::: "memory");
        }
        __syncthreads();
        if (it + 2 < niter) ISSUE((it + 2) % 3, (it + 2) << 5);

        int st = it % 3;
        const __half* AshH = sm + st*STH;
        const __half* BshW = AshH + TILE;

        #pragma unroll
        for (int ks = 0; ks < 2; ks++) {
            uint32_t aH[2][4];
            #pragma unroll
            for (int mi = 0; mi < 2; mi++) {
                int row = wm + mi*16 + (lane & 15);
                int col = ks*16 + ((lane >> 4) << 3);
                ldsm4(aH[mi], &AshH[row*40 + col]);
            }
            uint32_t bW[8][2];
            #pragma unroll
            for (int pi = 0; pi < 4; pi++) {
                int nr = wn + pi*16 + ((lane >> 4) << 3) + (lane & 7);
                int kc = ks*16 + (((lane >> 3) & 1) << 3);
                uint32_t t[4];
                ldsm4(t, &BshW[nr*40 + kc]);
                bW[2*pi][0] = t[0]; bW[2*pi][1] = t[1];
                bW[2*pi+1][0] = t[2]; bW[2*pi+1][1] = t[3];
            }
            #pragma unroll
            for (int mi = 0; mi < 2; mi++)
                #pragma unroll
                for (int nj = 0; nj < 8; nj++)
                    mma_f16(acc[mi][nj], aH[mi], bW[nj]);
        }
    }
    #undef ISSUE

    int g = lane >> 2, tg = lane & 3;
    #pragma unroll
    for (int mi = 0; mi < 2; mi++)
        #pragma unroll
        for (int nj = 0; nj < 8; nj++) {
            int r0 = bm + wm + mi*16 + g;
            int c0 = bn + wn + nj*8 + tg*2;
            float v[4];
            #pragma unroll
            for (int q = 0; q < 4; q++) {
                float x = acc[mi][nj][q];
                if (HASBIAS) x += bias[c0 + (q & 1)];
                if (ACT == 1) x = tanhf(x);
                else if (ACT == 2) x = 0.5f * x * (1.0f + erff(x * 0.70710678f));
                v[q] = x;
            }
            if (PL == 1) {
                #pragma unroll
                for (int h2 = 0; h2 < 2; h2++) {
                    int r = r0 + h2*8;
                    __half2 hh;
                    hh.x = __float2half_rn(v[2*h2]);
                    hh.y = __float2half_rn(v[2*h2+1]);
                    *(__half2*)&outH[(size_t)r*N + c0] = hh;
                }
            } else {
                #pragma unroll
                for (int q = 0; q < 4; q++) {
                    int r = r0 + (q >> 1) * 8, c = c0 + (q & 1);
                    float x = v[q];
                    if (HASRES) {
                        int rr = GATH ? gmap(r) : r;
                        x += res[(size_t)rr * N + c];
                    }
                    out[(size_t)r * N + c] = x;
                }
            }
        }
}

// ---------------- standalone LayerNorm -> fp16 hi plane ----------------
__global__ __launch_bounds__(256) void ln_kernel(
    const float* __restrict__ x, const float* __restrict__ g,
    const float* __restrict__ b, __half* __restrict__ oh, int gather)
{
    int row = blockIdx.x;
    int src = gather ? ((row / Tt) * Lseq + 2 * (row % Tt) + 1) : row;
    float4 v = ((const float4*)(x + (size_t)src * Cc))[threadIdx.x];
    float s = v.x + v.y + v.z + v.w;
    float q = v.x*v.x + v.y*v.y + v.z*v.z + v.w*v.w;
    #pragma unroll
    for (int o = 16; o; o >>= 1) {
        s += __shfl_xor_sync(0xffffffffu, s, o);
        q += __shfl_xor_sync(0xffffffffu, q, o);
    }
    __shared__ float ss[8], sq[8];
    int w = threadIdx.x >> 5;
    if ((threadIdx.x & 31) == 0) { ss[w] = s; sq[w] = q; }
    __syncthreads();
    s = 0.f; q = 0.f;
    #pragma unroll
    for (int i = 0; i < 8; i++) { s += ss[i]; q += sq[i]; }
    float mean = s * (1.0f / Cc);
    float rstd = rsqrtf(q * (1.0f / Cc) - mean * mean + 1e-5f);
    float4 gv = ((const float4*)g)[threadIdx.x];
    float4 bv = ((const float4*)b)[threadIdx.x];
    size_t base = (size_t)row * Cc + threadIdx.x * 4;
    __half2 p;
    p.x = __float2half_rn((v.x - mean) * rstd * gv.x + bv.x);
    p.y = __float2half_rn((v.y - mean) * rstd * gv.y + bv.y);
    *(__half2*)&oh[base] = p;
    p.x = __float2half_rn((v.z - mean) * rstd * gv.z + bv.z);
    p.y = __float2half_rn((v.w - mean) * rstd * gv.w + bv.w);
    *(__half2*)&oh[base+2] = p;
}

// ---------------- token assembly ----------------
__global__ __launch_bounds__(256) void assemble_kernel(
    const float* __restrict__ SE, const int* __restrict__ actions,
    const int* __restrict__ tsteps, const float* __restrict__ act_table,
    const float* __restrict__ pos_emb, const float* __restrict__ gpe_table,
    float* __restrict__ x)
{
    int bt = blockIdx.x;
    int b = bt / Tt, t = bt % Tt;
    int a = actions[bt];
    int ts = tsteps[bt];
    size_t row0 = (size_t)(b * Lseq + 2*t) * Cc;
    for (int c = threadIdx.x; c < Cc; c += 256) {
        float gp = gpe_table[(size_t)ts * Cc + c];
        x[row0 + c]      = SE[(size_t)bt * Cc + c] + gp + pos_emb[(size_t)(2*t) * Cc + c];
        x[row0 + Cc + c] = tanhf(act_table[(size_t)a * Cc + c]) + gp + pos_emb[(size_t)(2*t+1) * Cc + c];
    }
}

// ---------------- MMA flash attention (fp16 1-term), 2-stage KV pipeline ----------------
// grid(L/64, B*H). Longest-first q-tile order: heavy tiles get wave-1 slots.
__global__ __launch_bounds__(128) void attn_kernel(
    const __half* __restrict__ QKVH, __half* __restrict__ OutH)
{
    extern __shared__ __half smb[];
    __half* sQ = smb;
    __half* sK0 = smb + 4608;
    __half* sK1 = smb + 2*4608;
    __half* sV0 = smb + 3*4608;
    __half* sV1 = smb + 4*4608;

    int tid = threadIdx.x, lane = tid & 31, wid = tid >> 5;
    int b = blockIdx.y >> 4, h = blockIdx.y & 15;
    int qi = gridDim.x - 1 - blockIdx.x;      // longest-first scheduling
    int q0 = qi * 64;
    size_t gbase = (size_t)b * Lseq * 3072 + h * 64;

    #pragma unroll
    for (int i = 0; i < 4; i++) {
        int id = tid + i*128;
        int r = (id >> 3) & 63;
        int c = (id & 7) << 3;
        cpa16(sQ + r*72 + c, QKVH + gbase + (size_t)(q0 + r)*3072 + c);
    }
    asm volatile("cp.async.commit_group;" ::: "memory");

    #define ISSUE_KV(J0, BK, BV) do {                                           \
        _Pragma("unroll")                                                       \
        for (int _i = 0; _i < 8; _i++) {                                        \
            int _id = tid + _i*128;                                             \
            int _pl = _id >> 9;                                                 \
            int _r = (_id >> 3) & 63;                                           \
            int _c = (_id & 7) << 3;                                            \
            cpa16((_pl ? (BV) : (BK)) + _r*72 + _c,                             \
                  QKVH + gbase + (size_t)((J0) + _r)*3072 + (_pl ? 2048 : 1024) + _c); \
        }                                                                       \
        asm volatile("cp.async.commit_group;" ::: "memory");                    \
    } while (0)

    ISSUE_KV(0, sK0, sV0);

    float m0 = -1e30f, m1 = -1e30f, lsum0 = 0.f, lsum1 = 0.f;
    float O[8][4];
    #pragma unroll
    for (int f = 0; f < 8; f++)
        #pragma unroll
        for (int q = 0; q < 4; q++) O[f][q] = 0.f;

    int g = lane >> 2, tg = lane & 3;
    int wq = wid * 16;
    int row0 = q0 + wq + g, row1 = row0 + 8;
    int ntiles = qi + 1;

    for (int kt = 0; kt < ntiles; kt++) {
        if (kt + 1 < ntiles) {
            if ((kt + 1) & 1) ISSUE_KV((kt+1)*64, sK1, sV1);
            else              ISSUE_KV((kt+1)*64, sK0, sV0);
            asm volatile("cp.async.wait_group 1;" ::: "memory");
        } else {
            asm volatile("cp.async.wait_group 0;" ::: "memory");
        }
        __syncthreads();
        const __half* sKH = (kt & 1) ? sK1 : sK0;
        const __half* sVH = (kt & 1) ? sV1 : sV0;
        int j0 = kt * 64;

        float S[8][4];
        #pragma unroll
        for (int f = 0; f < 8; f++)
            #pragma unroll
            for (int q = 0; q < 4; q++) S[f][q] = 0.f;

        #pragma unroll
        for (int ks = 0; ks < 4; ks++) {
            int arow = wq + (lane & 15);
            int acol = ks*16 + ((lane >> 4) << 3);
            uint32_t aH[4];
            ldsm4(aH, sQ + arow*72 + acol);
            #pragma unroll
            for (int nb = 0; nb < 4; nb++) {
                int nr = nb*16 + ((lane >> 4) << 3) + (lane & 7);
                int kc = ks*16 + (((lane >> 3) & 1) << 3);
                uint32_t tK[4];
                ldsm4(tK, sKH + nr*72 + kc);
                uint32_t b0[2] = {tK[0], tK[1]}, b1[2] = {tK[2], tK[3]};
                mma_f16(S[2*nb],   aH, b0);
                mma_f16(S[2*nb+1], aH, b1);
            }
        }

        #pragma unroll
        for (int f = 0; f < 8; f++) {
            int kcol = j0 + f*8 + tg*2;
            float v0 = S[f][0]*0.125f; if (kcol   > row0) v0 = -1e30f;
            float v1 = S[f][1]*0.125f; if (kcol+1 > row0) v1 = -1e30f;
            float v2 = S[f][2]*0.125f; if (kcol   > row1) v2 = -1e30f;
            float v3 = S[f][3]*0.125f; if (kcol+1 > row1) v3 = -1e30f;
            S[f][0] = v0; S[f][1] = v1; S[f][2] = v2; S[f][3] = v3;
        }
        float r0m = -1e30f, r1m = -1e30f;
        #pragma unroll
        for (int f = 0; f < 8; f++) {
            r0m = fmaxf(r0m, fmaxf(S[f][0], S[f][1]));
            r1m = fmaxf(r1m, fmaxf(S[f][2], S[f][3]));
        }
        r0m = fmaxf(r0m, __shfl_xor_sync(0xffffffffu, r0m, 1));
        r0m = fmaxf(r0m, __shfl_xor_sync(0xffffffffu, r0m, 2));
        r1m = fmaxf(r1m, __shfl_xor_sync(0xffffffffu, r1m, 1));
        r1m = fmaxf(r1m, __shfl_xor_sync(0xffffffffu, r1m, 2));
        float mn0 = fmaxf(m0, r0m), mn1 = fmaxf(m1, r1m);
        float a0 = fast_exp(m0 - mn0), a1 = fast_exp(m1 - mn1);
        m0 = mn0; m1 = mn1;

        float s0 = 0.f, s1 = 0.f;
        #pragma unroll
        for (int f = 0; f < 8; f++) {
            float p0 = fast_exp(S[f][0] - mn0);
            float p1 = fast_exp(S[f][1] - mn0);
            float p2 = fast_exp(S[f][2] - mn1);
            float p3 = fast_exp(S[f][3] - mn1);
            S[f][0] = p0; S[f][1] = p1; S[f][2] = p2; S[f][3] = p3;
            s0 += p0 + p1; s1 += p2 + p3;
        }
        s0 += __shfl_xor_sync(0xffffffffu, s0, 1);
        s0 += __shfl_xor_sync(0xffffffffu, s0, 2);
        s1 += __shfl_xor_sync(0xffffffffu, s1, 1);
        s1 += __shfl_xor_sync(0xffffffffu, s1, 2);
        lsum0 = lsum0 * a0 + s0;
        lsum1 = lsum1 * a1 + s1;
        #pragma unroll
        for (int f = 0; f < 8; f++) {
            O[f][0] *= a0; O[f][1] *= a0;
            O[f][2] *= a1; O[f][3] *= a1;
        }

        #pragma unroll
        for (int ks2 = 0; ks2 < 4; ks2++) {
            uint32_t pH[4];
            #pragma unroll
            for (int hf = 0; hf < 2; hf++) {
                int f = 2*ks2 + hf;
                __half2 t;
                t.x = __float2half_rn(S[f][0]);
                t.y = __float2half_rn(S[f][1]);
                pH[hf*2+0] = *(uint32_t*)&t;
                t.x = __float2half_rn(S[f][2]);
                t.y = __float2half_rn(S[f][3]);
                pH[hf*2+1] = *(uint32_t*)&t;
            }
            int vrow = ks2*16 + (lane & 15);
            #pragma unroll
            for (int nb = 0; nb < 4; nb++) {
                int vcol = nb*16 + ((lane >> 4) << 3);
                uint32_t tV[4];
                ldsm4t(tV, sVH + vrow*72 + vcol);
                uint32_t b0[2] = {tV[0], tV[1]}, b1[2] = {tV[2], tV[3]};
                mma_f16(O[2*nb],   pH, b0);
                mma_f16(O[2*nb+1], pH, b1);
            }
        }
        __syncthreads();
    }
    #undef ISSUE_KV

    float rl0 = 1.f / lsum0, rl1 = 1.f / lsum1;
    size_t t0 = (size_t)(b*Lseq + row0), t1 = (size_t)(b*Lseq + row1);
    #pragma unroll
    for (int f = 0; f < 8; f++) {
        int gcol = h*64 + f*8 + tg*2;
        __half2 ph;
        ph.x = __float2half_rn(O[f][0]*rl0);
        ph.y = __float2half_rn(O[f][1]*rl0);
        *(__half2*)&OutH[t0*Cc + gcol] = ph;
        ph.x = __float2half_rn(O[f][2]*rl1);
        ph.y = __float2half_rn(O[f][3]*rl1);
        *(__half2*)&OutH[t1*Cc + gcol] = ph;
    }
}

// ---------------- weight transpose + fp16 (generic) ----------------
__global__ __launch_bounds__(256) void wsplit_kernel(
    const float* __restrict__ W, __half* __restrict__ Wh, int K, int N,
    size_t inStride, size_t outStride)
{
    const float* Wz = W + (size_t)blockIdx.z * inStride;
    __half* Whz = Wh + (size_t)blockIdx.z * outStride;
    __shared__ float tile[32][33];
    int k0 = blockIdx.y * 32, n0 = blockIdx.x * 32;
    int tx = threadIdx.x & 31, ty = threadIdx.x >> 5;
    #pragma unroll
    for (int r = ty; r < 32; r += 8)
        tile[r][tx] = Wz[(size_t)(k0 + r) * N + n0 + tx];
    __syncthreads();
    #pragma unroll
    for (int r = ty; r < 32; r += 8)
        Whz[(size_t)(n0 + r) * K + k0 + tx] = __float2half_rn(tile[tx][r]);
}

// ---------------- merged wsplit: Wq/Wk/Wv/Wo ----------------
__global__ __launch_bounds__(256) void wsplit4_kernel(
    const float* __restrict__ Wq, const float* __restrict__ Wk,
    const float* __restrict__ Wv, const float* __restrict__ Wo,
    __half* __restrict__ wAll)
{
    int z = blockIdx.z;
    int m = z >> 3, lyr = z & 7;
    const float* W = (m == 0 ? Wq : m == 1 ? Wk : m == 2 ? Wv : Wo)
                   + (size_t)lyr * Cc * Cc;
    uint32_t doff = (m == 0) ? OFF_QKVs
                  : (m == 1) ? OFF_QKVs + 1024u*Cc
                  : (m == 2) ? OFF_QKVs + 2048u*Cc : OFF_WOs;
    __half* out = wAll + (size_t)lyr * LWs + doff;

    __shared__ float tile[32][33];
    int k0 = blockIdx.y * 32, n0 = blockIdx.x * 32;
    int tx = threadIdx.x & 31, ty = threadIdx.x >> 5;
    #pragma unroll
    for (int r = ty; r < 32; r += 8)
        tile[r][tx] = W[(size_t)(k0 + r) * Cc + n0 + tx];
    __syncthreads();
    #pragma unroll
    for (int r = ty; r < 32; r += 8)
        out[(size_t)(n0 + r) * Cc + k0 + tx] = __float2half_rn(tile[tx][r]);
}

// ---------------- merged wsplit: W1 + W2 ----------------
__global__ __launch_bounds__(256) void wsplit12_kernel(
    const float* __restrict__ W1, const float* __restrict__ W2,
    __half* __restrict__ wAll)
{
    int z = blockIdx.z;
    int m = z >> 3, lyr = z & 7;
    int K = m ? 2048 : 1024;
    int N = m ? 1024 : 2048;
    int k0 = blockIdx.y * 32, n0 = blockIdx.x * 32;
    if (k0 >= K || n0 >= N) return;
    const float* W = (m ? W2 : W1) + (size_t)lyr * 2097152;
    __half* out = wAll + (size_t)lyr * LWs + (m ? OFF_W2s : OFF_W1s);

    __shared__ float tile[32][33];
    int tx = threadIdx.x & 31, ty = threadIdx.x >> 5;
    #pragma unroll
    for (int r = ty; r < 32; r += 8)
        tile[r][tx] = W[(size_t)(k0 + r) * N + n0 + tx];
    __syncthreads();
    #pragma unroll
    for (int r = ty; r < 32; r += 8)
        out[(size_t)(n0 + r) * K + k0 + tx] = __float2half_rn(tile[tx][r]);
}

// ---------------- fused QKV bias concat ----------------
__global__ __launch_bounds__(256) void bcat_kernel(
    const float* __restrict__ bq, const float* __restrict__ bk,
    const float* __restrict__ bv, float* __restrict__ outb)
{
    int i = blockIdx.x * 256 + threadIdx.x;
    if (i < NLAYER * 3072) {
        int lyr = i / 3072, c = i % 3072;
        float v = (c < 1024) ? bq[lyr*1024 + c]
                : (c < 2048) ? bk[lyr*1024 + c - 1024]
                             : bv[lyr*1024 + c - 2048];
        outb[i] = v;
    }
}

// ---------------- elementwise fp16 round (states) ----------------
__global__ __launch_bounds__(256) void esplit1_kernel(
    const float* __restrict__ x, __half* __restrict__ h, int n)
{
    int i = (blockIdx.x * 256 + threadIdx.x) * 4;
    if (i < n) {
        float4 v = *(const float4*)&x[i];
        __half2 p;
        p.x = __float2half_rn(v.x); p.y = __float2half_rn(v.y);
        *(__half2*)&h[i] = p;
        p.x = __float2half_rn(v.z); p.y = __float2half_rn(v.w);
        *(__half2*)&h[i+2] = p;
    }
}

// ---------------- launcher ----------------
extern "C" void kernel_launch(void* const* d_in, const int* in_sizes, int n_in,
                              void* d_out, int out_size) {
    const float* states   = (const float*)d_in[0];
    const int*   actions  = (const int*)d_in[1];
    const int*   tsteps   = (const int*)d_in[2];
    const float* W_se     = (const float*)d_in[3];
    const float* b_se     = (const float*)d_in[4];
    const float* act_tab  = (const float*)d_in[5];
    const float* pos_emb  = (const float*)d_in[6];
    const float* gpe      = (const float*)d_in[7];
    const float* ln1_g    = (const float*)d_in[8];
    const float* ln1_b    = (const float*)d_in[9];
    const float* Wq       = (const float*)d_in[10];
    const float* bq       = (const float*)d_in[11];
    const float* Wk       = (const float*)d_in[12];
    const float* bk       = (const float*)d_in[13];
    const float* Wv       = (const float*)d_in[14];
    const float* bv       = (const float*)d_in[15];
    const float* Wo       = (const float*)d_in[16];
    const float* bo       = (const float*)d_in[17];
    const float* ln2_g    = (const float*)d_in[18];
    const float* ln2_b    = (const float*)d_in[19];
    const float* W1       = (const float*)d_in[20];
    const float* b1       = (const float*)d_in[21];
    const float* W2       = (const float*)d_in[22];
    const float* b2       = (const float*)d_in[23];
    const float* lnf_g    = (const float*)d_in[24];
    const float* lnf_b    = (const float*)d_in[25];
    const float* W_head   = (const float*)d_in[26];
    float* out = (float*)d_out;

    float* F = nullptr;
    cudaGetSymbolAddress((void**)&F, g_f32);
    float* BQKV = nullptr;
    cudaGetSymbolAddress((void**)&BQKV, g_bqkv);
    __half* HP = nullptr;
    cudaGetSymbolAddress((void**)&HP, g_hp);

    float* X  = F;
    float* X2 = X  + N_BLC;
    float* HF = X2 + N_BLC;

    size_t off = 0;
    auto take = [&](size_t n) { __half* p = HP + off; off += n; return p; };
    __half *stH = take(524288);
    __half *wseH = take(131072);
    __half *wAll = take(67108864);
    __half *hdH = take(4194304);
    __half *HbH = take(N_BLC);
    __half *AOH = take(N_BLC);
    __half *MIDH = take(2*N_BLC);
    __half *HFH = take(N_HF);
    __half *QKVH = take(3*N_BLC);

    const int GSM1 = 3*2*5120*2;        // 61440 B
    const int ATSM = 5*4608*2;          // 46080 B
    cudaFuncSetAttribute(gemm_hk<1,true,false,0,false>, cudaFuncAttributeMaxDynamicSharedMemorySize, GSM1);
    cudaFuncSetAttribute(gemm_hk<0,true,false,1,false>, cudaFuncAttributeMaxDynamicSharedMemorySize, GSM1);
    cudaFuncSetAttribute(gemm_hk<0,true,true,0,false>,  cudaFuncAttributeMaxDynamicSharedMemorySize, GSM1);
    cudaFuncSetAttribute(gemm_hk<0,true,true,0,true>,   cudaFuncAttributeMaxDynamicSharedMemorySize, GSM1);
    cudaFuncSetAttribute(gemm_hk<2,true,false,1,false>, cudaFuncAttributeMaxDynamicSharedMemorySize, GSM1);
    cudaFuncSetAttribute(gemm_hk<0,false,false,0,false>,cudaFuncAttributeMaxDynamicSharedMemorySize, GSM1);
    cudaFuncSetAttribute(attn_kernel, cudaFuncAttributeMaxDynamicSharedMemorySize, ATSM);

    const int Mx = Bb * Lseq;   // 8192
    const int Mh = Bb * Tt;     // 4096
    dim3 thr(256);

    // ---- prep ----
    bcat_kernel<<<96, thr>>>(bq, bk, bv, BQKV);
    esplit1_kernel<<<512, thr>>>(states, stH, Mh * Ss);
    wsplit_kernel<<<dim3(Cc/32, Ss/32, 1), thr>>>(W_se, wseH, Ss, Cc, 0, 0);
    wsplit4_kernel<<<dim3(32, 32, 32), thr>>>(Wq, Wk, Wv, Wo, wAll);
    wsplit12_kernel<<<dim3(64, 64, 16), thr>>>(W1, W2, wAll);

    // ---- state encoder + token assembly ----
    gemm_hk<1,true,false,0,false><<<dim3(Cc/128, Mh/128), thr, GSM1>>>(
        stH, wseH, b_se, nullptr, HF, nullptr, Mh, Cc, Ss);
    assemble_kernel<<<Mh, thr>>>(HF, actions, tsteps, act_tab, pos_emb, gpe, X);

    for (int lyr = 0; lyr < NLAYER; lyr++) {
        __half* wqkv = wAll + lyr*LWs + OFF_QKVs;
        __half* wo   = wAll + lyr*LWs + OFF_WOs;
        __half* w1   = wAll + lyr*LWs + OFF_W1s;
        __half* w2   = wAll + lyr*LWs + OFF_W2s;
        bool last = (lyr == NLAYER - 1);

        ln_kernel<<<Mx, thr>>>(X, ln1_g + lyr*Cc, ln1_b + lyr*Cc, HbH, 0);
        gemm_hk<0,true,false,1,false><<<dim3(3072/128, Mx/128), thr, GSM1>>>(
            HbH, wqkv, BQKV + lyr*3072, nullptr, nullptr, QKVH, Mx, 3072, Cc);
        attn_kernel<<<dim3(Lseq/64, Bb*16), dim3(128), ATSM>>>(QKVH, AOH);
        if (!last) {
            gemm_hk<0,true,true,0,false><<<dim3(Cc/128, Mx/128), thr, GSM1>>>(
                AOH, wo, bo + lyr*Cc, X, X2, nullptr, Mx, Cc, Cc);
            ln_kernel<<<Mx, thr>>>(X2, ln2_g + lyr*Cc, ln2_b + lyr*Cc, HbH, 0);
            gemm_hk<2,true,false,1,false><<<dim3(2*Cc/128, Mx/128), thr, GSM1>>>(
                HbH, w1, b1 + lyr*2*Cc, nullptr, nullptr, MIDH, Mx, 2*Cc, Cc);
            gemm_hk<0,true,true,0,false><<<dim3(Cc/128, Mx/128), thr, GSM1>>>(
                MIDH, w2, b2 + lyr*Cc, X2, X, nullptr, Mx, Cc, 2*Cc);
        } else {
            // last layer: only odd rows survive -> compact M=4096 path
            gemm_hk<0,true,true,0,true><<<dim3(Cc/128, Mh/128), thr, GSM1>>>(
                AOH, wo, bo + lyr*Cc, X, X2, nullptr, Mh, Cc, Cc);
            ln_kernel<<<Mh, thr>>>(X2, ln2_g + lyr*Cc, ln2_b + lyr*Cc, HbH, 0);
            gemm_hk<2,true,false,1,false><<<dim3(2*Cc/128, Mh/128), thr, GSM1>>>(
                HbH, w1, b1 + lyr*2*Cc, nullptr, nullptr, MIDH, Mh, 2*Cc, Cc);
            gemm_hk<0,true,true,0,false><<<dim3(Cc/128, Mh/128), thr, GSM1>>>(
                MIDH, w2, b2 + lyr*Cc, X2, HF, nullptr, Mh, Cc, 2*Cc);
        }
    }

    wsplit_kernel<<<dim3(VOC/32, Cc/32, 1), thr>>>(W_head, hdH, Cc, VOC, 0, 0);
    ln_kernel<<<Mh, thr>>>(HF, lnf_g, lnf_b, HFH, 0);
    gemm_hk<0,false,false,0,false><<<dim3(VOC/128, Mh/128), thr, GSM1>>>(
        HFH, hdH, nullptr, nullptr, out, nullptr, Mh, VOC, Cc);
}

// round 17
// speedup vs baseline: 1.0615x; 1.0134x over previous
#include <cuda_runtime.h>
#include <cuda_fp16.h>
#include <cstdint>

#define Bb 4
#define Tt 1024
#define Ss 128
#define Cc 1024
#define NLAYER 8
#define VOC 4096
#define Lseq 2048

#define N_BLC (Bb*Lseq*Cc)
#define N_HF  (Bb*Tt*Cc)

__device__ float g_f32[2*N_BLC + N_HF];       // X, X2, HF
__device__ float g_bqkv[NLAYER*3072];         // fused qkv bias
__device__ __half g_hp[198311936];            // all fp16 planes

#define LWs 8388608u
#define OFF_QKVs 0u
#define OFF_WOs 3145728u
#define OFF_W1s 4194304u
#define OFF_W2s 6291456u

// ---------------- helpers ----------------
__device__ __forceinline__ int gmap(int r) {          // compact idx -> odd row in [B*L)
    return ((r >> 10) << 11) + ((r & 1023) << 1) + 1;
}
__device__ __forceinline__ void ldsm4(uint32_t r[4], const __half* p) {
    uint32_t a = (uint32_t)__cvta_generic_to_shared(p);
    asm volatile("ldmatrix.sync.aligned.m8n8.x4.shared.b16 {%0,%1,%2,%3}, [%4];"
        : "=r"(r[0]), "=r"(r[1]), "=r"(r[2]), "=r"(r[3]) : "r"(a));
}
__device__ __forceinline__ void ldsm4t(uint32_t r[4], const __half* p) {
    uint32_t a = (uint32_t)__cvta_generic_to_shared(p);
    asm volatile("ldmatrix.sync.aligned.m8n8.x4.trans.shared.b16 {%0,%1,%2,%3}, [%4];"
        : "=r"(r[0]), "=r"(r[1]), "=r"(r[2]), "=r"(r[3]) : "r"(a));
}
__device__ __forceinline__ void mma_f16(float c[4], const uint32_t a[4], const uint32_t b[2]) {
    asm volatile("mma.sync.aligned.m16n8k16.row.col.f32.f16.f16.f32 "
        "{%0,%1,%2,%3}, {%4,%5,%6,%7}, {%8,%9}, {%0,%1,%2,%3};"
        : "+f"(c[0]), "+f"(c[1]), "+f"(c[2]), "+f"(c[3])
        : "r"(a[0]), "r"(a[1]), "r"(a[2]), "r"(a[3]), "r"(b[0]), "r"(b[1]));
}
__device__ __forceinline__ void cpa16(__half* dst, const __half* src) {
    uint32_t d = (uint32_t)__cvta_generic_to_shared(dst);
    asm volatile("cp.async.cg.shared.global [%0], [%1], 16;" :: "r"(d), "l"(src));
}
__device__ __forceinline__ float fast_exp(float x) {
    x = fmaxf(x, -80.f);
    float y = x * 1.44269504088896f;
    float t = y + 12582912.f;
    int ni = __float_as_int(t) - 0x4B400000;
    float f = y - (t - 12582912.f);
    float p = 1.33335581e-3f;
    p = fmaf(p, f, 9.61812910e-3f);
    p = fmaf(p, f, 5.55041087e-2f);
    p = fmaf(p, f, 2.40226507e-1f);
    p = fmaf(p, f, 6.93147180e-1f);
    p = fmaf(p, f, 1.0f);
    return p * __int_as_float((ni + 127) << 23);
}

// ---------------- GEMM: out = act((A)@W16^T + bias)(+res) ----------------
// CTA 128x128, BK=32, 8 warps of 32x64, 3-stage cp.async.
// GATHA: A-rows via odd-row map.  GATHR: res-rows via odd-row map.
template<int ACT, bool HASBIAS, bool HASRES, int PL, bool GATHA, bool GATHR>
__global__ __launch_bounds__(256, 2) void gemm_hk(
    const __half* __restrict__ Ah, const __half* __restrict__ Wh,
    const float* __restrict__ bias, const float* __restrict__ res,
    float* __restrict__ out, __half* __restrict__ outH,
    int M, int N, int K)
{
    extern __shared__ __half sm[];
    const int TILE = 128*40;
    const int STH = 2 * TILE;
    int tid = threadIdx.x, lane = tid & 31, warp = tid >> 5;
    int bm = blockIdx.y * 128, bn = blockIdx.x * 128;
    int wm = (warp >> 1) * 32, wn = (warp & 1) * 64;

    float acc[2][8][4];
    #pragma unroll
    for (int i = 0; i < 2; i++)
        #pragma unroll
        for (int j = 0; j < 8; j++)
            #pragma unroll
            for (int q = 0; q < 4; q++) acc[i][j][q] = 0.f;

    int niter = K >> 5;

    #define ISSUE(ST, K0) do {                                                  \
        int _k0 = (K0);                                                         \
        _Pragma("unroll")                                                       \
        for (int _i = 0; _i < 4; _i++) {                                        \
            int _id = tid + (_i << 8);                                          \
            int _tile = _id >> 9;                                               \
            int _r = (_id >> 2) & 127;                                          \
            int _c = (_id & 3) << 3;                                            \
            const __half* _src;                                                 \
            if (_tile == 0) {                                                   \
                int _row = GATHA ? gmap(bm + _r) : (bm + _r);                   \
                _src = Ah + (size_t)_row * K + _k0 + _c;                        \
            } else {                                                            \
                _src = Wh + (size_t)(bn + _r) * K + _k0 + _c;                   \
            }                                                                   \
            cpa16(sm + (ST)*STH + _tile*TILE + _r*40 + _c, _src);               \
        }                                                                       \
        asm volatile("cp.async.commit_group;" ::: "memory");                    \
    } while (0)

    ISSUE(0, 0);
    if (niter > 1) ISSUE(1, 32);
    for (int it = 0; it < niter; ++it) {
        if (it + 1 < niter) {
            asm volatile("cp.async.wait_group 1;" ::: "memory");
        } else {
            asm volatile("cp.async.wait_group 0;" ::: "memory");
        }
        __syncthreads();
        if (it + 2 < niter) ISSUE((it + 2) % 3, (it + 2) << 5);

        int st = it % 3;
        const __half* AshH = sm + st*STH;
        const __half* BshW = AshH + TILE;

        #pragma unroll
        for (int ks = 0; ks < 2; ks++) {
            uint32_t aH[2][4];
            #pragma unroll
            for (int mi = 0; mi < 2; mi++) {
                int row = wm + mi*16 + (lane & 15);
                int col = ks*16 + ((lane >> 4) << 3);
                ldsm4(aH[mi], &AshH[row*40 + col]);
            }
            uint32_t bW[8][2];
            #pragma unroll
            for (int pi = 0; pi < 4; pi++) {
                int nr = wn + pi*16 + ((lane >> 4) << 3) + (lane & 7);
                int kc = ks*16 + (((lane >> 3) & 1) << 3);
                uint32_t t[4];
                ldsm4(t, &BshW[nr*40 + kc]);
                bW[2*pi][0] = t[0]; bW[2*pi][1] = t[1];
                bW[2*pi+1][0] = t[2]; bW[2*pi+1][1] = t[3];
            }
            #pragma unroll
            for (int mi = 0; mi < 2; mi++)
                #pragma unroll
                for (int nj = 0; nj < 8; nj++)
                    mma_f16(acc[mi][nj], aH[mi], bW[nj]);
        }
    }
    #undef ISSUE

    int g = lane >> 2, tg = lane & 3;
    #pragma unroll
    for (int mi = 0; mi < 2; mi++)
        #pragma unroll
        for (int nj = 0; nj < 8; nj++) {
            int r0 = bm + wm + mi*16 + g;
            int c0 = bn + wn + nj*8 + tg*2;
            float v[4];
            #pragma unroll
            for (int q = 0; q < 4; q++) {
                float x = acc[mi][nj][q];
                if (HASBIAS) x += bias[c0 + (q & 1)];
                if (ACT == 1) x = tanhf(x);
                else if (ACT == 2) x = 0.5f * x * (1.0f + erff(x * 0.70710678f));
                v[q] = x;
            }
            if (PL == 1) {
                #pragma unroll
                for (int h2 = 0; h2 < 2; h2++) {
                    int r = r0 + h2*8;
                    __half2 hh;
                    hh.x = __float2half_rn(v[2*h2]);
                    hh.y = __float2half_rn(v[2*h2+1]);
                    *(__half2*)&outH[(size_t)r*N + c0] = hh;
                }
            } else {
                #pragma unroll
                for (int q = 0; q < 4; q++) {
                    int r = r0 + (q >> 1) * 8, c = c0 + (q & 1);
                    float x = v[q];
                    if (HASRES) {
                        int rr = GATHR ? gmap(r) : r;
                        x += res[(size_t)rr * N + c];
                    }
                    out[(size_t)r * N + c] = x;
                }
            }
        }
}

// ---------------- standalone LayerNorm -> fp16 hi plane ----------------
__global__ __launch_bounds__(256) void ln_kernel(
    const float* __restrict__ x, const float* __restrict__ g,
    const float* __restrict__ b, __half* __restrict__ oh, int gather)
{
    int row = blockIdx.x;
    int src = gather ? ((row / Tt) * Lseq + 2 * (row % Tt) + 1) : row;
    float4 v = ((const float4*)(x + (size_t)src * Cc))[threadIdx.x];
    float s = v.x + v.y + v.z + v.w;
    float q = v.x*v.x + v.y*v.y + v.z*v.z + v.w*v.w;
    #pragma unroll
    for (int o = 16; o; o >>= 1) {
        s += __shfl_xor_sync(0xffffffffu, s, o);
        q += __shfl_xor_sync(0xffffffffu, q, o);
    }
    __shared__ float ss[8], sq[8];
    int w = threadIdx.x >> 5;
    if ((threadIdx.x & 31) == 0) { ss[w] = s; sq[w] = q; }
    __syncthreads();
    s = 0.f; q = 0.f;
    #pragma unroll
    for (int i = 0; i < 8; i++) { s += ss[i]; q += sq[i]; }
    float mean = s * (1.0f / Cc);
    float rstd = rsqrtf(q * (1.0f / Cc) - mean * mean + 1e-5f);
    float4 gv = ((const float4*)g)[threadIdx.x];
    float4 bv = ((const float4*)b)[threadIdx.x];
    size_t base = (size_t)row * Cc + threadIdx.x * 4;
    __half2 p;
    p.x = __float2half_rn((v.x - mean) * rstd * gv.x + bv.x);
    p.y = __float2half_rn((v.y - mean) * rstd * gv.y + bv.y);
    *(__half2*)&oh[base] = p;
    p.x = __float2half_rn((v.z - mean) * rstd * gv.z + bv.z);
    p.y = __float2half_rn((v.w - mean) * rstd * gv.w + bv.w);
    *(__half2*)&oh[base+2] = p;
}

// ---------------- token assembly ----------------
__global__ __launch_bounds__(256) void assemble_kernel(
    const float* __restrict__ SE, const int* __restrict__ actions,
    const int* __restrict__ tsteps, const float* __restrict__ act_table,
    const float* __restrict__ pos_emb, const float* __restrict__ gpe_table,
    float* __restrict__ x)
{
    int bt = blockIdx.x;
    int b = bt / Tt, t = bt % Tt;
    int a = actions[bt];
    int ts = tsteps[bt];
    size_t row0 = (size_t)(b * Lseq + 2*t) * Cc;
    for (int c = threadIdx.x; c < Cc; c += 256) {
        float gp = gpe_table[(size_t)ts * Cc + c];
        x[row0 + c]      = SE[(size_t)bt * Cc + c] + gp + pos_emb[(size_t)(2*t) * Cc + c];
        x[row0 + Cc + c] = tanhf(act_table[(size_t)a * Cc + c]) + gp + pos_emb[(size_t)(2*t+1) * Cc + c];
    }
}

// ---------------- MMA flash attention (fp16 1-term), 2-stage KV pipeline ----------------
// LASTQ=false: grid(L/64, B*H), full query rows.
// LASTQ=true : grid(T/64, B*H), only odd query rows (compact), output compact [B*T, C].
template<bool LASTQ>
__global__ __launch_bounds__(128) void attn_kernel(
    const __half* __restrict__ QKVH, __half* __restrict__ OutH)
{
    extern __shared__ __half smb[];
    __half* sQ = smb;
    __half* sK0 = smb + 4608;
    __half* sK1 = smb + 2*4608;
    __half* sV0 = smb + 3*4608;
    __half* sV1 = smb + 4*4608;

    int tid = threadIdx.x, lane = tid & 31, wid = tid >> 5;
    int b = blockIdx.y >> 4, h = blockIdx.y & 15;
    int qi = gridDim.x - 1 - blockIdx.x;      // longest-first scheduling
    int q0 = qi * 64;                          // compact (LASTQ) or global q base
    size_t gbase = (size_t)b * Lseq * 3072 + h * 64;

    #pragma unroll
    for (int i = 0; i < 4; i++) {
        int id = tid + i*128;
        int r = (id >> 3) & 63;
        int c = (id & 7) << 3;
        int grow = LASTQ ? (2*(q0 + r) + 1) : (q0 + r);
        cpa16(sQ + r*72 + c, QKVH + gbase + (size_t)grow*3072 + c);
    }
    asm volatile("cp.async.commit_group;" ::: "memory");

    #define ISSUE_KV(J0, BK, BV) do {                                           \
        _Pragma("unroll")                                                       \
        for (int _i = 0; _i < 8; _i++) {                                        \
            int _id = tid + _i*128;                                             \
            int _pl = _id >> 9;                                                 \
            int _r = (_id >> 3) & 63;                                           \
            int _c = (_id & 7) << 3;                                            \
            cpa16((_pl ? (BV) : (BK)) + _r*72 + _c,                             \
                  QKVH + gbase + (size_t)((J0) + _r)*3072 + (_pl ? 2048 : 1024) + _c); \
        }                                                                       \
        asm volatile("cp.async.commit_group;" ::: "memory");                    \
    } while (0)

    ISSUE_KV(0, sK0, sV0);

    float m0 = -1e30f, m1 = -1e30f, lsum0 = 0.f, lsum1 = 0.f;
    float O[8][4];
    #pragma unroll
    for (int f = 0; f < 8; f++)
        #pragma unroll
        for (int q = 0; q < 4; q++) O[f][q] = 0.f;

    int g = lane >> 2, tg = lane & 3;
    int wq = wid * 16;
    // global key-comparison rows
    int row0 = LASTQ ? (2*(q0 + wq + g) + 1) : (q0 + wq + g);
    int row1 = LASTQ ? (row0 + 16) : (row0 + 8);
    int ntiles = LASTQ ? (2*qi + 2) : (qi + 1);

    for (int kt = 0; kt < ntiles; kt++) {
        if (kt + 1 < ntiles) {
            if ((kt + 1) & 1) ISSUE_KV((kt+1)*64, sK1, sV1);
            else              ISSUE_KV((kt+1)*64, sK0, sV0);
            asm volatile("cp.async.wait_group 1;" ::: "memory");
        } else {
            asm volatile("cp.async.wait_group 0;" ::: "memory");
        }
        __syncthreads();
        const __half* sKH = (kt & 1) ? sK1 : sK0;
        const __half* sVH = (kt & 1) ? sV1 : sV0;
        int j0 = kt * 64;

        float S[8][4];
        #pragma unroll
        for (int f = 0; f < 8; f++)
            #pragma unroll
            for (int q = 0; q < 4; q++) S[f][q] = 0.f;

        #pragma unroll
        for (int ks = 0; ks < 4; ks++) {
            int arow = wq + (lane & 15);
            int acol = ks*16 + ((lane >> 4) << 3);
            uint32_t aH[4];
            ldsm4(aH, sQ + arow*72 + acol);
            #pragma unroll
            for (int nb = 0; nb < 4; nb++) {
                int nr = nb*16 + ((lane >> 4) << 3) + (lane & 7);
                int kc = ks*16 + (((lane >> 3) & 1) << 3);
                uint32_t tK[4];
                ldsm4(tK, sKH + nr*72 + kc);
                uint32_t b0[2] = {tK[0], tK[1]}, b1[2] = {tK[2], tK[3]};
                mma_f16(S[2*nb],   aH, b0);
                mma_f16(S[2*nb+1], aH, b1);
            }
        }

        #pragma unroll
        for (int f = 0; f < 8; f++) {
            int kcol = j0 + f*8 + tg*2;
            float v0 = S[f][0]*0.125f; if (kcol   > row0) v0 = -1e30f;
            float v1 = S[f][1]*0.125f; if (kcol+1 > row0) v1 = -1e30f;
            float v2 = S[f][2]*0.125f; if (kcol   > row1) v2 = -1e30f;
            float v3 = S[f][3]*0.125f; if (kcol+1 > row1) v3 = -1e30f;
            S[f][0] = v0; S[f][1] = v1; S[f][2] = v2; S[f][3] = v3;
        }
        float r0m = -1e30f, r1m = -1e30f;
        #pragma unroll
        for (int f = 0; f < 8; f++) {
            r0m = fmaxf(r0m, fmaxf(S[f][0], S[f][1]));
            r1m = fmaxf(r1m, fmaxf(S[f][2], S[f][3]));
        }
        r0m = fmaxf(r0m, __shfl_xor_sync(0xffffffffu, r0m, 1));
        r0m = fmaxf(r0m, __shfl_xor_sync(0xffffffffu, r0m, 2));
        r1m = fmaxf(r1m, __shfl_xor_sync(0xffffffffu, r1m, 1));
        r1m = fmaxf(r1m, __shfl_xor_sync(0xffffffffu, r1m, 2));
        float mn0 = fmaxf(m0, r0m), mn1 = fmaxf(m1, r1m);
        float a0 = fast_exp(m0 - mn0), a1 = fast_exp(m1 - mn1);
        m0 = mn0; m1 = mn1;

        float s0 = 0.f, s1 = 0.f;
        #pragma unroll
        for (int f = 0; f < 8; f++) {
            float p0 = fast_exp(S[f][0] - mn0);
            float p1 = fast_exp(S[f][1] - mn0);
            float p2 = fast_exp(S[f][2] - mn1);
            float p3 = fast_exp(S[f][3] - mn1);
            S[f][0] = p0; S[f][1] = p1; S[f][2] = p2; S[f][3] = p3;
            s0 += p0 + p1; s1 += p2 + p3;
        }
        s0 += __shfl_xor_sync(0xffffffffu, s0, 1);
        s0 += __shfl_xor_sync(0xffffffffu, s0, 2);
        s1 += __shfl_xor_sync(0xffffffffu, s1, 1);
        s1 += __shfl_xor_sync(0xffffffffu, s1, 2);
        lsum0 = lsum0 * a0 + s0;
        lsum1 = lsum1 * a1 + s1;
        #pragma unroll
        for (int f = 0; f < 8; f++) {
            O[f][0] *= a0; O[f][1] *= a0;
            O[f][2] *= a1; O[f][3] *= a1;
        }

        #pragma unroll
        for (int ks2 = 0; ks2 < 4; ks2++) {
            uint32_t pH[4];
            #pragma unroll
            for (int hf = 0; hf < 2; hf++) {
                int f = 2*ks2 + hf;
                __half2 t;
                t.x = __float2half_rn(S[f][0]);
                t.y = __float2half_rn(S[f][1]);
                pH[hf*2+0] = *(uint32_t*)&t;
                t.x = __float2half_rn(S[f][2]);
                t.y = __float2half_rn(S[f][3]);
                pH[hf*2+1] = *(uint32_t*)&t;
            }
            int vrow = ks2*16 + (lane & 15);
            #pragma unroll
            for (int nb = 0; nb < 4; nb++) {
                int vcol = nb*16 + ((lane >> 4) << 3);
                uint32_t tV[4];
                ldsm4t(tV, sVH + vrow*72 + vcol);
                uint32_t b0[2] = {tV[0], tV[1]}, b1[2] = {tV[2], tV[3]};
                mma_f16(O[2*nb],   pH, b0);
                mma_f16(O[2*nb+1], pH, b1);
            }
        }
        __syncthreads();
    }
    #undef ISSUE_KV

    float rl0 = 1.f / lsum0, rl1 = 1.f / lsum1;
    size_t t0, t1;
    if (LASTQ) {
        int rc0 = q0 + wq + g;                 // compact row
        t0 = (size_t)(b*Tt + rc0);
        t1 = (size_t)(b*Tt + rc0 + 8);
    } else {
        t0 = (size_t)(b*Lseq + row0);
        t1 = (size_t)(b*Lseq + row1);
    }
    #pragma unroll
    for (int f = 0; f < 8; f++) {
        int gcol = h*64 + f*8 + tg*2;
        __half2 ph;
        ph.x = __float2half_rn(O[f][0]*rl0);
        ph.y = __float2half_rn(O[f][1]*rl0);
        *(__half2*)&OutH[t0*Cc + gcol] = ph;
        ph.x = __float2half_rn(O[f][2]*rl1);
        ph.y = __float2half_rn(O[f][3]*rl1);
        *(__half2*)&OutH[t1*Cc + gcol] = ph;
    }
}

// ---------------- weight transpose + fp16 (generic) ----------------
__global__ __launch_bounds__(256) void wsplit_kernel(
    const float* __restrict__ W, __half* __restrict__ Wh, int K, int N,
    size_t inStride, size_t outStride)
{
    const float* Wz = W + (size_t)blockIdx.z * inStride;
    __half* Whz = Wh + (size_t)blockIdx.z * outStride;
    __shared__ float tile[32][33];
    int k0 = blockIdx.y * 32, n0 = blockIdx.x * 32;
    int tx = threadIdx.x & 31, ty = threadIdx.x >> 5;
    #pragma unroll
    for (int r = ty; r < 32; r += 8)
        tile[r][tx] = Wz[(size_t)(k0 + r) * N + n0 + tx];
    __syncthreads();
    #pragma unroll
    for (int r = ty; r < 32; r += 8)
        Whz[(size_t)(n0 + r) * K + k0 + tx] = __float2half_rn(tile[tx][r]);
}

// ---------------- merged wsplit: Wq/Wk/Wv/Wo ----------------
__global__ __launch_bounds__(256) void wsplit4_kernel(
    const float* __restrict__ Wq, const float* __restrict__ Wk,
    const float* __restrict__ Wv, const float* __restrict__ Wo,
    __half* __restrict__ wAll)
{
    int z = blockIdx.z;
    int m = z >> 3, lyr = z & 7;
    const float* W = (m == 0 ? Wq : m == 1 ? Wk : m == 2 ? Wv : Wo)
                   + (size_t)lyr * Cc * Cc;
    uint32_t doff = (m == 0) ? OFF_QKVs
                  : (m == 1) ? OFF_QKVs + 1024u*Cc
                  : (m == 2) ? OFF_QKVs + 2048u*Cc : OFF_WOs;
    __half* out = wAll + (size_t)lyr * LWs + doff;

    __shared__ float tile[32][33];
    int k0 = blockIdx.y * 32, n0 = blockIdx.x * 32;
    int tx = threadIdx.x & 31, ty = threadIdx.x >> 5;
    #pragma unroll
    for (int r = ty; r < 32; r += 8)
        tile[r][tx] = W[(size_t)(k0 + r) * Cc + n0 + tx];
    __syncthreads();
    #pragma unroll
    for (int r = ty; r < 32; r += 8)
        out[(size_t)(n0 + r) * Cc + k0 + tx] = __float2half_rn(tile[tx][r]);
}

// ---------------- merged wsplit: W1 + W2 ----------------
__global__ __launch_bounds__(256) void wsplit12_kernel(
    const float* __restrict__ W1, const float* __restrict__ W2,
    __half* __restrict__ wAll)
{
    int z = blockIdx.z;
    int m = z >> 3, lyr = z & 7;
    int K = m ? 2048 : 1024;
    int N = m ? 1024 : 2048;
    int k0 = blockIdx.y * 32, n0 = blockIdx.x * 32;
    if (k0 >= K || n0 >= N) return;
    const float* W = (m ? W2 : W1) + (size_t)lyr * 2097152;
    __half* out = wAll + (size_t)lyr * LWs + (m ? OFF_W2s : OFF_W1s);

    __shared__ float tile[32][33];
    int tx = threadIdx.x & 31, ty = threadIdx.x >> 5;
    #pragma unroll
    for (int r = ty; r < 32; r += 8)
        tile[r][tx] = W[(size_t)(k0 + r) * N + n0 + tx];
    __syncthreads();
    #pragma unroll
    for (int r = ty; r < 32; r += 8)
        out[(size_t)(n0 + r) * K + k0 + tx] = __float2half_rn(tile[tx][r]);
}

// ---------------- fused QKV bias concat ----------------
__global__ __launch_bounds__(256) void bcat_kernel(
    const float* __restrict__ bq, const float* __restrict__ bk,
    const float* __restrict__ bv, float* __restrict__ outb)
{
    int i = blockIdx.x * 256 + threadIdx.x;
    if (i < NLAYER * 3072) {
        int lyr = i / 3072, c = i % 3072;
        float v = (c < 1024) ? bq[lyr*1024 + c]
                : (c < 2048) ? bk[lyr*1024 + c - 1024]
                             : bv[lyr*1024 + c - 2048];
        outb[i] = v;
    }
}

// ---------------- elementwise fp16 round (states) ----------------
__global__ __launch_bounds__(256) void esplit1_kernel(
    const float* __restrict__ x, __half* __restrict__ h, int n)
{
    int i = (blockIdx.x * 256 + threadIdx.x) * 4;
    if (i < n) {
        float4 v = *(const float4*)&x[i];
        __half2 p;
        p.x = __float2half_rn(v.x); p.y = __float2half_rn(v.y);
        *(__half2*)&h[i] = p;
        p.x = __float2half_rn(v.z); p.y = __float2half_rn(v.w);
        *(__half2*)&h[i+2] = p;
    }
}

// ---------------- launcher ----------------
extern "C" void kernel_launch(void* const* d_in, const int* in_sizes, int n_in,
                              void* d_out, int out_size) {
    const float* states   = (const float*)d_in[0];
    const int*   actions  = (const int*)d_in[1];
    const int*   tsteps   = (const int*)d_in[2];
    const float* W_se     = (const float*)d_in[3];
    const float* b_se     = (const float*)d_in[4];
    const float* act_tab  = (const float*)d_in[5];
    const float* pos_emb  = (const float*)d_in[6];
    const float* gpe      = (const float*)d_in[7];
    const float* ln1_g    = (const float*)d_in[8];
    const float* ln1_b    = (const float*)d_in[9];
    const float* Wq       = (const float*)d_in[10];
    const float* bq       = (const float*)d_in[11];
    const float* Wk       = (const float*)d_in[12];
    const float* bk       = (const float*)d_in[13];
    const float* Wv       = (const float*)d_in[14];
    const float* bv       = (const float*)d_in[15];
    const float* Wo       = (const float*)d_in[16];
    const float* bo       = (const float*)d_in[17];
    const float* ln2_g    = (const float*)d_in[18];
    const float* ln2_b    = (const float*)d_in[19];
    const float* W1       = (const float*)d_in[20];
    const float* b1       = (const float*)d_in[21];
    const float* W2       = (const float*)d_in[22];
    const float* b2       = (const float*)d_in[23];
    const float* lnf_g    = (const float*)d_in[24];
    const float* lnf_b    = (const float*)d_in[25];
    const float* W_head   = (const float*)d_in[26];
    float* out = (float*)d_out;

    float* F = nullptr;
    cudaGetSymbolAddress((void**)&F, g_f32);
    float* BQKV = nullptr;
    cudaGetSymbolAddress((void**)&BQKV, g_bqkv);
    __half* HP = nullptr;
    cudaGetSymbolAddress((void**)&HP, g_hp);

    float* X  = F;
    float* X2 = X  + N_BLC;
    float* HF = X2 + N_BLC;

    size_t off = 0;
    auto take = [&](size_t n) { __half* p = HP + off; off += n; return p; };
    __half *stH = take(524288);
    __half *wseH = take(131072);
    __half *wAll = take(67108864);
    __half *hdH = take(4194304);
    __half *HbH = take(N_BLC);
    __half *AOH = take(N_BLC);
    __half *MIDH = take(2*N_BLC);
    __half *HFH = take(N_HF);
    __half *QKVH = take(3*N_BLC);

    const int GSM1 = 3*2*5120*2;        // 61440 B
    const int ATSM = 5*4608*2;          // 46080 B
    cudaFuncSetAttribute(gemm_hk<1,true,false,0,false,false>, cudaFuncAttributeMaxDynamicSharedMemorySize, GSM1);
    cudaFuncSetAttribute(gemm_hk<0,true,false,1,false,false>, cudaFuncAttributeMaxDynamicSharedMemorySize, GSM1);
    cudaFuncSetAttribute(gemm_hk<0,true,true,0,false,false>,  cudaFuncAttributeMaxDynamicSharedMemorySize, GSM1);
    cudaFuncSetAttribute(gemm_hk<0,true,true,0,false,true>,   cudaFuncAttributeMaxDynamicSharedMemorySize, GSM1);
    cudaFuncSetAttribute(gemm_hk<2,true,false,1,false,false>, cudaFuncAttributeMaxDynamicSharedMemorySize, GSM1);
    cudaFuncSetAttribute(gemm_hk<0,false,false,0,false,false>,cudaFuncAttributeMaxDynamicSharedMemorySize, GSM1);
    cudaFuncSetAttribute(attn_kernel<false>, cudaFuncAttributeMaxDynamicSharedMemorySize, ATSM);
    cudaFuncSetAttribute(attn_kernel<true>,  cudaFuncAttributeMaxDynamicSharedMemorySize, ATSM);

    const int Mx = Bb * Lseq;   // 8192
    const int Mh = Bb * Tt;     // 4096
    dim3 thr(256);

    // ---- prep ----
    bcat_kernel<<<96, thr>>>(bq, bk, bv, BQKV);
    esplit1_kernel<<<512, thr>>>(states, stH, Mh * Ss);
    wsplit_kernel<<<dim3(Cc/32, Ss/32, 1), thr>>>(W_se, wseH, Ss, Cc, 0, 0);
    wsplit4_kernel<<<dim3(32, 32, 32), thr>>>(Wq, Wk, Wv, Wo, wAll);
    wsplit12_kernel<<<dim3(64, 64, 16), thr>>>(W1, W2, wAll);

    // ---- state encoder + token assembly ----
    gemm_hk<1,true,false,0,false,false><<<dim3(Cc/128, Mh/128), thr, GSM1>>>(
        stH, wseH, b_se, nullptr, HF, nullptr, Mh, Cc, Ss);
    assemble_kernel<<<Mh, thr>>>(HF, actions, tsteps, act_tab, pos_emb, gpe, X);

    for (int lyr = 0; lyr < NLAYER; lyr++) {
        __half* wqkv = wAll + lyr*LWs + OFF_QKVs;
        __half* wo   = wAll + lyr*LWs + OFF_WOs;
        __half* w1   = wAll + lyr*LWs + OFF_W1s;
        __half* w2   = wAll + lyr*LWs + OFF_W2s;
        bool last = (lyr == NLAYER - 1);

        ln_kernel<<<Mx, thr>>>(X, ln1_g + lyr*Cc, ln1_b + lyr*Cc, HbH, 0);
        gemm_hk<0,true,false,1,false,false><<<dim3(3072/128, Mx/128), thr, GSM1>>>(
            HbH, wqkv, BQKV + lyr*3072, nullptr, nullptr, QKVH, Mx, 3072, Cc);
        if (!last) {
            attn_kernel<false><<<dim3(Lseq/64, Bb*16), dim3(128), ATSM>>>(QKVH, AOH);
            gemm_hk<0,true,true,0,false,false><<<dim3(Cc/128, Mx/128), thr, GSM1>>>(
                AOH, wo, bo + lyr*Cc, X, X2, nullptr, Mx, Cc, Cc);
            ln_kernel<<<Mx, thr>>>(X2, ln2_g + lyr*Cc, ln2_b + lyr*Cc, HbH, 0);
            gemm_hk<2,true,false,1,false,false><<<dim3(2*Cc/128, Mx/128), thr, GSM1>>>(
                HbH, w1, b1 + lyr*2*Cc, nullptr, nullptr, MIDH, Mx, 2*Cc, Cc);
            gemm_hk<0,true,true,0,false,false><<<dim3(Cc/128, Mx/128), thr, GSM1>>>(
                MIDH, w2, b2 + lyr*Cc, X2, X, nullptr, Mx, Cc, 2*Cc);
        } else {
            // last layer: only odd rows survive -> odd-Q attention + compact M=4096 path
            attn_kernel<true><<<dim3(Tt/64, Bb*16), dim3(128), ATSM>>>(QKVH, AOH);
            gemm_hk<0,true,true,0,false,true><<<dim3(Cc/128, Mh/128), thr, GSM1>>>(
                AOH, wo, bo + lyr*Cc, X, X2, nullptr, Mh, Cc, Cc);
            ln_kernel<<<Mh, thr>>>(X2, ln2_g + lyr*Cc, ln2_b + lyr*Cc, HbH, 0);
            gemm_hk<2,true,false,1,false,false><<<dim3(2*Cc/128, Mh/128), thr, GSM1>>>(
                HbH, w1, b1 + lyr*2*Cc, nullptr, nullptr, MIDH, Mh, 2*Cc, Cc);
            gemm_hk<0,true,true,0,false,false><<<dim3(Cc/128, Mh/128), thr, GSM1>>>(
                MIDH, w2, b2 + lyr*Cc, X2, HF, nullptr, Mh, Cc, 2*Cc);
        }
    }

    wsplit_kernel<<<dim3(VOC/32, Cc/32, 1), thr>>>(W_head, hdH, Cc, VOC, 0, 0);
    ln_kernel<<<Mh, thr>>>(HF, lnf_g, lnf_b, HFH, 0);
    gemm_hk<0,false,false,0,false,false><<<dim3(VOC/128, Mh/128), thr, GSM1>>>(
        HFH, hdH, nullptr, nullptr, out, nullptr, Mh, VOC, Cc);
}